// round 2
// baseline (speedup 1.0000x reference)
#include <cuda_runtime.h>
#include <cuda_bf16.h>
#include <cstdint>

#define B_ROWS 4096
#define D_IN   1024
#define HID    32768
#define TOPK   32
#define NCAND  48      // candidate selection target (margin over 32)
#define CAP    96      // candidate capacity per row

// ---------------- static device scratch (no allocs allowed) ----------------
__device__ __nv_bfloat16 g_Wb[(size_t)HID * D_IN];      // bf16 W_enc (67 MB)
__device__ __nv_bfloat16 g_xb[(size_t)B_ROWS * D_IN];   // bf16 (x - b_dec) (8 MB)
__device__ __nv_bfloat16 g_pre[(size_t)B_ROWS * HID];   // approx pre_acts (256 MB)
__device__ int   g_cand[B_ROWS * CAP];
__device__ int   g_ncand[B_ROWS];
__device__ float g_topv[B_ROWS * TOPK];
__device__ int   g_topi[B_ROWS * TOPK];

// ---------------- converters ----------------
__global__ void k_convW(const float* __restrict__ W) {
    size_t n = (size_t)HID * D_IN;
    for (size_t i = (size_t)blockIdx.x * blockDim.x + threadIdx.x; i < n;
         i += (size_t)gridDim.x * blockDim.x)
        g_Wb[i] = __float2bfloat16(W[i]);
}

__global__ void k_convX(const float* __restrict__ x, const float* __restrict__ b_dec) {
    size_t n = (size_t)B_ROWS * D_IN;
    for (size_t i = (size_t)blockIdx.x * blockDim.x + threadIdx.x; i < n;
         i += (size_t)gridDim.x * blockDim.x) {
        int d = (int)(i & (D_IN - 1));
        g_xb[i] = __float2bfloat16(x[i] - b_dec[d]);
    }
}

// ---------------- GEMM: pre = relu((x-b_dec) @ W_enc^T + b_enc), bf16 out ----
// Tile 128x128, BK=32. smem tiles packed 2 logical rows (64B) per 128B phys row,
// XOR swizzle for conflict-free ldmatrix.
#define BM 128
#define BN 128
#define BK 32
#define KT (D_IN / BK)   // 32 k-tiles

__device__ __forceinline__ uint32_t swz32(uint32_t r, uint32_t c) {
    uint32_t pr = r >> 1;
    uint32_t pc = (c + ((r & 1u) << 2)) ^ (pr & 7u);
    return pr * 128u + (pc << 4);
}

__global__ __launch_bounds__(256) void k_gemm(const float* __restrict__ b_enc) {
    __shared__ __align__(16) uint8_t smem[2 * 16384];  // stage: A 8KB + B 8KB

    const int tid  = threadIdx.x;
    const int wid  = tid >> 5;
    const int lane = tid & 31;
    const int bm0  = blockIdx.y * BM;
    const int bn0  = blockIdx.x * BN;
    const int warp_m = (wid >> 2) * 64;  // 2 warps along M
    const int warp_n = (wid & 3) * 32;   // 4 warps along N

    float acc[4][4][4];
    #pragma unroll
    for (int a = 0; a < 4; a++)
        #pragma unroll
        for (int b = 0; b < 4; b++)
            #pragma unroll
            for (int c = 0; c < 4; c++) acc[a][b][c] = 0.f;

    auto issueLoads = [&](int kt, int stage) {
        const __nv_bfloat16* Asrc = g_xb + (size_t)bm0 * D_IN + kt * BK;
        const __nv_bfloat16* Bsrc = g_Wb + (size_t)bn0 * D_IN + kt * BK;
        uint8_t* As = smem + stage * 16384;
        uint8_t* Bs = As + 8192;
        #pragma unroll
        for (int i = 0; i < 2; i++) {
            int id = tid + 256 * i;
            int r = id >> 2, c = id & 3;
            uint32_t da = (uint32_t)__cvta_generic_to_shared(As + swz32(r, c));
            const void* sa = Asrc + (size_t)r * D_IN + c * 8;
            asm volatile("cp.async.cg.shared.global [%0], [%1], 16;\n" :: "r"(da), "l"(sa));
            uint32_t db = (uint32_t)__cvta_generic_to_shared(Bs + swz32(r, c));
            const void* sb = Bsrc + (size_t)r * D_IN + c * 8;
            asm volatile("cp.async.cg.shared.global [%0], [%1], 16;\n" :: "r"(db), "l"(sb));
        }
        asm volatile("cp.async.commit_group;\n" ::: "memory");
    };

    auto computeStage = [&](int stage) {
        uint8_t* As = smem + stage * 16384;
        uint8_t* Bs = As + 8192;
        #pragma unroll
        for (int ks = 0; ks < 2; ks++) {
            uint32_t a[4][4], b[2][4];
            #pragma unroll
            for (int im = 0; im < 4; im++) {
                int r = warp_m + im * 16 + (lane & 15);
                int c = ks * 2 + (lane >> 4);
                uint32_t addr = (uint32_t)__cvta_generic_to_shared(As + swz32(r, c));
                asm volatile("ldmatrix.sync.aligned.m8n8.x4.shared.b16 {%0,%1,%2,%3}, [%4];\n"
                             : "=r"(a[im][0]), "=r"(a[im][1]), "=r"(a[im][2]), "=r"(a[im][3])
                             : "r"(addr));
            }
            #pragma unroll
            for (int in2 = 0; in2 < 2; in2++) {
                int r = warp_n + in2 * 16 + (lane & 7) + ((lane & 16) ? 8 : 0);
                int c = ks * 2 + ((lane >> 3) & 1);
                uint32_t addr = (uint32_t)__cvta_generic_to_shared(Bs + swz32(r, c));
                asm volatile("ldmatrix.sync.aligned.m8n8.x4.shared.b16 {%0,%1,%2,%3}, [%4];\n"
                             : "=r"(b[in2][0]), "=r"(b[in2][1]), "=r"(b[in2][2]), "=r"(b[in2][3])
                             : "r"(addr));
            }
            #pragma unroll
            for (int im = 0; im < 4; im++)
                #pragma unroll
                for (int in8 = 0; in8 < 4; in8++) {
                    uint32_t b0 = b[in8 >> 1][(in8 & 1) * 2 + 0];
                    uint32_t b1 = b[in8 >> 1][(in8 & 1) * 2 + 1];
                    float* c4 = acc[im][in8];
                    asm volatile(
                        "mma.sync.aligned.m16n8k16.row.col.f32.bf16.bf16.f32 "
                        "{%0,%1,%2,%3},{%4,%5,%6,%7},{%8,%9},{%0,%1,%2,%3};\n"
                        : "+f"(c4[0]), "+f"(c4[1]), "+f"(c4[2]), "+f"(c4[3])
                        : "r"(a[im][0]), "r"(a[im][1]), "r"(a[im][2]), "r"(a[im][3]),
                          "r"(b0), "r"(b1));
                }
        }
    };

    issueLoads(0, 0);
    for (int kt = 0; kt < KT; kt++) {
        asm volatile("cp.async.wait_group 0;\n" ::: "memory");
        __syncthreads();
        if (kt + 1 < KT) issueLoads(kt + 1, (kt + 1) & 1);
        computeStage(kt & 1);
        __syncthreads();
    }

    // epilogue: + b_enc, relu, bf16 store
    const int r0 = bm0 + warp_m + (lane >> 2);
    const int c0 = bn0 + warp_n + (lane & 3) * 2;
    #pragma unroll
    for (int im = 0; im < 4; im++)
        #pragma unroll
        for (int in8 = 0; in8 < 4; in8++) {
            int r = r0 + im * 16;
            int h = c0 + in8 * 8;
            float be0 = b_enc[h], be1 = b_enc[h + 1];
            float v0 = acc[im][in8][0] + be0; v0 = (v0 > 0.f) ? v0 : 0.f;
            float v1 = acc[im][in8][1] + be1; v1 = (v1 > 0.f) ? v1 : 0.f;
            float v2 = acc[im][in8][2] + be0; v2 = (v2 > 0.f) ? v2 : 0.f;
            float v3 = acc[im][in8][3] + be1; v3 = (v3 > 0.f) ? v3 : 0.f;
            __nv_bfloat162 p01;
            p01.x = __float2bfloat16(v0); p01.y = __float2bfloat16(v1);
            *(__nv_bfloat162*)&g_pre[(size_t)r * HID + h] = p01;
            __nv_bfloat162 p23;
            p23.x = __float2bfloat16(v2); p23.y = __float2bfloat16(v3);
            *(__nv_bfloat162*)&g_pre[(size_t)(r + 8) * HID + h] = p23;
        }
}

// ---------------- per-row top-NCAND candidate selection (2-level radix) -----
__global__ __launch_bounds__(256) void k_select() {
    const int row = blockIdx.x;
    const uint16_t* kp = reinterpret_cast<const uint16_t*>(g_pre + (size_t)row * HID);
    __shared__ int hist[256];
    __shared__ int sB1, sCntGt, sThr, sCnt;
    const int tid = threadIdx.x;

    hist[tid] = 0;
    __syncthreads();
    for (int i = tid; i < HID; i += 256) atomicAdd(&hist[kp[i] >> 8], 1);
    __syncthreads();
    if (tid == 0) {
        int cum = 0, b;
        for (b = 255; b > 0; b--) {
            if (cum + hist[b] >= NCAND) break;
            cum += hist[b];
        }
        sB1 = b; sCntGt = cum;
    }
    __syncthreads();
    const int B1 = sB1, cntGt = sCntGt;
    hist[tid] = 0;
    __syncthreads();
    for (int i = tid; i < HID; i += 256) {
        uint16_t k = kp[i];
        if ((k >> 8) == B1) atomicAdd(&hist[k & 255], 1);
    }
    __syncthreads();
    if (tid == 0) {
        int cum = cntGt, l;
        for (l = 255; l > 0; l--) {
            if (cum + hist[l] >= NCAND) break;
            cum += hist[l];
        }
        sThr = (B1 << 8) | l;
        sCnt = 0;
    }
    __syncthreads();
    const uint16_t thr = (uint16_t)sThr;
    for (int i = tid; i < HID; i += 256) {
        if (kp[i] >= thr) {
            int p = atomicAdd(&sCnt, 1);
            if (p < CAP) g_cand[row * CAP + p] = i;
        }
    }
    __syncthreads();
    if (tid == 0) g_ncand[row] = min(sCnt, CAP);
}

// ---------------- exact recompute of candidates + top-32 --------------------
__global__ __launch_bounds__(256) void k_exact(const float* __restrict__ x,
                                               const float* __restrict__ b_dec,
                                               const float* __restrict__ W,
                                               const float* __restrict__ b_enc) {
    const int row = blockIdx.x;
    __shared__ float sae[D_IN];
    __shared__ float vals[CAP];
    __shared__ int   cidx[CAP];
    const int tid = threadIdx.x, lane = tid & 31, wid = tid >> 5;

    for (int i = tid; i < D_IN; i += 256) sae[i] = x[(size_t)row * D_IN + i] - b_dec[i];
    const int nc = g_ncand[row];
    for (int i = tid; i < nc; i += 256) cidx[i] = g_cand[row * CAP + i];
    __syncthreads();

    for (int c = wid; c < nc; c += 8) {
        const int h = cidx[c];
        const float* wr = W + (size_t)h * D_IN;
        double accd = 0.0;
        for (int j = lane; j < D_IN; j += 32) accd += (double)(sae[j] * wr[j]);
        for (int o = 16; o; o >>= 1) accd += __shfl_down_sync(0xffffffffu, accd, o);
        if (lane == 0) {
            float v = (float)accd + b_enc[h];
            vals[c] = (v > 0.f) ? v : 0.f;
        }
    }
    __syncthreads();

    if (wid == 0) {
        for (int t = 0; t < TOPK; t++) {
            float bv = -1.f; int bi = 0x7fffffff; int bc = -1;
            for (int c = lane; c < nc; c += 32) {
                float v = vals[c]; int h = cidx[c];
                if (v > bv || (v == bv && h < bi)) { bv = v; bi = h; bc = c; }
            }
            #pragma unroll
            for (int o = 16; o; o >>= 1) {
                float ov = __shfl_down_sync(0xffffffffu, bv, o);
                int   oi = __shfl_down_sync(0xffffffffu, bi, o);
                int   oc = __shfl_down_sync(0xffffffffu, bc, o);
                if (ov > bv || (ov == bv && oi < bi)) { bv = ov; bi = oi; bc = oc; }
            }
            bv = __shfl_sync(0xffffffffu, bv, 0);
            bi = __shfl_sync(0xffffffffu, bi, 0);
            bc = __shfl_sync(0xffffffffu, bc, 0);
            if (lane == 0) {
                g_topv[row * TOPK + t] = (bc >= 0 && bv > 0.f) ? bv : 0.f;
                g_topi[row * TOPK + t] = (bc >= 0) ? bi : 0;
                if (bc >= 0) vals[bc] = -2.f;
            }
            __syncwarp();
        }
    }
}

// ---------------- decode: out = sum_t v_t * W_dec[idx_t] + b_dec ------------
__global__ __launch_bounds__(256) void k_decode(const float* __restrict__ W_dec,
                                                const float* __restrict__ b_dec,
                                                float* __restrict__ out) {
    const int row = blockIdx.x;
    const int tid = threadIdx.x;
    __shared__ float v[TOPK];
    __shared__ int   hi[TOPK];
    if (tid < TOPK) {
        v[tid]  = g_topv[row * TOPK + tid];
        hi[tid] = g_topi[row * TOPK + tid];
    }
    __syncthreads();
    float acc0 = 0.f, acc1 = 0.f, acc2 = 0.f, acc3 = 0.f;
    #pragma unroll 1
    for (int t = 0; t < TOPK; t++) {
        const float* wr = W_dec + (size_t)hi[t] * D_IN;
        const float vt = v[t];
        acc0 += vt * wr[tid];
        acc1 += vt * wr[tid + 256];
        acc2 += vt * wr[tid + 512];
        acc3 += vt * wr[tid + 768];
    }
    float* o = out + (size_t)row * D_IN;
    o[tid]       = acc0 + b_dec[tid];
    o[tid + 256] = acc1 + b_dec[tid + 256];
    o[tid + 512] = acc2 + b_dec[tid + 512];
    o[tid + 768] = acc3 + b_dec[tid + 768];
}

// ---------------- launcher ----------------
extern "C" void kernel_launch(void* const* d_in, const int* in_sizes, int n_in,
                              void* d_out, int out_size) {
    const float* x     = (const float*)d_in[0];
    const float* W_enc = (const float*)d_in[1];
    const float* b_enc = (const float*)d_in[2];
    const float* W_dec = (const float*)d_in[3];
    const float* b_dec = (const float*)d_in[4];
    float* out = (float*)d_out;

    k_convW<<<4096, 256>>>(W_enc);
    k_convX<<<512, 256>>>(x, b_dec);

    dim3 g(HID / BN, B_ROWS / BM);
    k_gemm<<<g, 256>>>(b_enc);

    k_select<<<B_ROWS, 256>>>();
    k_exact<<<B_ROWS, 256>>>(x, b_dec, W_enc, b_enc);
    k_decode<<<B_ROWS, 256>>>(W_dec, b_dec, out);
}